// round 2
// baseline (speedup 1.0000x reference)
#include <cuda_runtime.h>

// Problem constants
#define NN   4096
#define EE   131072
#define ETOT (EE + NN)

// ---------------- device scratch (no allocs allowed) ----------------
__device__ int   d_f64;            // 1 if edge_index is int64, 0 if int32
__device__ int   d_cnt[NN];
__device__ int   d_wp[NN];
__device__ int   d_rp[NN + 1];
__device__ int   d_esrc[ETOT];

__device__ float d_xl[NN * 512];
__device__ float d_h[NN * 512];
__device__ float d_res[NN * 512];
__device__ float d_gat[NN * 512];
__device__ float d_als[NN * 4];
__device__ float d_ald[NN * 4];
__device__ float d_h2[NN * 256];
__device__ float d_Q[NN * 256];
__device__ float d_Kb[NN * 256];
__device__ float d_Vb[NN * 256];
__device__ float d_att[NN * 256];

// ---------------- tf32 helpers ----------------
__device__ __forceinline__ unsigned f2tf(float f) {
    unsigned u;
    asm("cvt.rna.tf32.f32 %0, %1;" : "=r"(u) : "f"(f));
    return u;
}
__device__ __forceinline__ void mma_tf32(float c[4],
                                         unsigned a0, unsigned a1, unsigned a2, unsigned a3,
                                         unsigned b0, unsigned b1) {
    asm volatile(
        "mma.sync.aligned.m16n8k8.row.col.f32.tf32.tf32.f32 "
        "{%0,%1,%2,%3}, {%4,%5,%6,%7}, {%8,%9}, {%0,%1,%2,%3};"
        : "+f"(c[0]), "+f"(c[1]), "+f"(c[2]), "+f"(c[3])
        : "r"(a0), "r"(a1), "r"(a2), "r"(a3), "r"(b0), "r"(b1));
}

// ---------------- edge index access (dtype-agnostic) ----------------
__global__ void k_detect(const unsigned* ei) {
    if (blockIdx.x == 0 && threadIdx.x == 0) {
        int f = 1;
        for (int i = 1; i < 128; i += 2) {
            if (ei[i] != 0u) { f = 0; break; }
        }
        d_f64 = f;
    }
}

__device__ __forceinline__ int eget(const void* p, long long i) {
    if (d_f64) return (int)(((const long long*)p)[i]);
    return ((const int*)p)[i];
}

// ---------------- CSR build ----------------
__global__ void k_zero_cnt() {
    int i = blockIdx.x * blockDim.x + threadIdx.x;
    if (i < NN) d_cnt[i] = 0;
}

__global__ void k_count(const void* ei) {
    int e = blockIdx.x * blockDim.x + threadIdx.x;
    if (e >= ETOT) return;
    int d = (e < EE) ? eget(ei, (long long)EE + e) : (e - EE);
    atomicAdd(&d_cnt[d], 1);
}

__global__ void k_scan() {
    __shared__ int sh[1024];
    int t = threadIdx.x;
    int v[4];
    int tot = 0;
#pragma unroll
    for (int i = 0; i < 4; i++) { v[i] = d_cnt[t * 4 + i]; tot += v[i]; }
    sh[t] = tot;
    __syncthreads();
    for (int off = 1; off < 1024; off <<= 1) {
        int x = (t >= off) ? sh[t - off] : 0;
        __syncthreads();
        sh[t] += x;
        __syncthreads();
    }
    int base = sh[t] - tot;
    int run = base;
#pragma unroll
    for (int i = 0; i < 4; i++) {
        d_rp[t * 4 + i] = run;
        d_wp[t * 4 + i] = run;
        run += v[i];
    }
    if (t == 1023) d_rp[NN] = run;
}

__global__ void k_scatter(const void* ei) {
    int e = blockIdx.x * blockDim.x + threadIdx.x;
    if (e >= ETOT) return;
    int s, d;
    if (e < EE) { s = eget(ei, e); d = eget(ei, (long long)EE + e); }
    else        { s = d = e - EE; }
    int pos = atomicAdd(&d_wp[d], 1);
    d_esrc[pos] = s;
}

// ---------------- tf32 tensor-core GEMM: C[M,Nd] = A[M,Kd] @ B[Kd,Nd] (+bias)
// block tile 128x64, BK=32, 256 threads = 8 warps (4 x 2), warp tile 32x32
__global__ void __launch_bounds__(256) k_gemm_tc(const float* __restrict__ A,
                                                 const float* __restrict__ B,
                                                 const float* __restrict__ bias,
                                                 float* __restrict__ C,
                                                 int M, int Kd, int Nd) {
    __shared__ float As[128][36];   // tf32 bits, stride 36 -> conflict-free a-frags
    __shared__ float Bs[32][68];    // tf32 bits
    int t = threadIdx.x, w = t >> 5, lane = t & 31;
    int gid = lane >> 2, tig = lane & 3;
    int wm = w >> 1, wn = w & 1;
    int m0 = blockIdx.y * 128, n0 = blockIdx.x * 64;

    float acc[2][4][4];
#pragma unroll
    for (int mi = 0; mi < 2; mi++)
#pragma unroll
        for (int nt = 0; nt < 4; nt++)
#pragma unroll
            for (int i = 0; i < 4; i++) acc[mi][nt][i] = 0.f;

    for (int k0 = 0; k0 < Kd; k0 += 32) {
        // load A tile 128x32 (cvt to tf32 at store)
#pragma unroll
        for (int i = 0; i < 4; i++) {
            int fi = t + i * 256;
            int row = fi >> 3, c4 = fi & 7;
            float4 v = *(const float4*)&A[(long)(m0 + row) * Kd + k0 + c4 * 4];
            float4 u;
            u.x = __uint_as_float(f2tf(v.x));
            u.y = __uint_as_float(f2tf(v.y));
            u.z = __uint_as_float(f2tf(v.z));
            u.w = __uint_as_float(f2tf(v.w));
            *(float4*)&As[row][c4 * 4] = u;
        }
        // load B tile 32x64
#pragma unroll
        for (int i = 0; i < 2; i++) {
            int fi = t + i * 256;
            int row = fi >> 4, c4 = fi & 15;
            float4 v = *(const float4*)&B[(long)(k0 + row) * Nd + n0 + c4 * 4];
            float4 u;
            u.x = __uint_as_float(f2tf(v.x));
            u.y = __uint_as_float(f2tf(v.y));
            u.z = __uint_as_float(f2tf(v.z));
            u.w = __uint_as_float(f2tf(v.w));
            *(float4*)&Bs[row][c4 * 4] = u;
        }
        __syncthreads();
#pragma unroll
        for (int kk = 0; kk < 4; kk++) {
            unsigned a[2][4], b[4][2];
#pragma unroll
            for (int mi = 0; mi < 2; mi++) {
                int r = wm * 32 + mi * 16;
                a[mi][0] = __float_as_uint(As[r + gid][kk * 8 + tig]);
                a[mi][1] = __float_as_uint(As[r + gid + 8][kk * 8 + tig]);
                a[mi][2] = __float_as_uint(As[r + gid][kk * 8 + tig + 4]);
                a[mi][3] = __float_as_uint(As[r + gid + 8][kk * 8 + tig + 4]);
            }
#pragma unroll
            for (int nt = 0; nt < 4; nt++) {
                b[nt][0] = __float_as_uint(Bs[kk * 8 + tig][wn * 32 + nt * 8 + gid]);
                b[nt][1] = __float_as_uint(Bs[kk * 8 + tig + 4][wn * 32 + nt * 8 + gid]);
            }
#pragma unroll
            for (int mi = 0; mi < 2; mi++)
#pragma unroll
                for (int nt = 0; nt < 4; nt++)
                    mma_tf32(acc[mi][nt], a[mi][0], a[mi][1], a[mi][2], a[mi][3],
                             b[nt][0], b[nt][1]);
        }
        __syncthreads();
    }
    // epilogue
#pragma unroll
    for (int mi = 0; mi < 2; mi++) {
#pragma unroll
        for (int nt = 0; nt < 4; nt++) {
            int row = m0 + wm * 32 + mi * 16 + gid;
            int col = n0 + wn * 32 + nt * 8 + 2 * tig;
            float b0 = bias ? bias[col] : 0.f;
            float b1 = bias ? bias[col + 1] : 0.f;
            float2 r0 = make_float2(acc[mi][nt][0] + b0, acc[mi][nt][1] + b1);
            float2 r1 = make_float2(acc[mi][nt][2] + b0, acc[mi][nt][3] + b1);
            *(float2*)&C[(long)row * Nd + col] = r0;
            *(float2*)&C[(long)(row + 8) * Nd + col] = r1;
        }
    }
}

// ---------------- per-node attention coefficients -------------------
__global__ void k_coef(const float* __restrict__ xl, const float* __restrict__ as_,
                       const float* __restrict__ ad_, int H, int C) {
    int gw = (blockIdx.x * blockDim.x + threadIdx.x) >> 5;
    int lane = threadIdx.x & 31;
    if (gw >= NN * H) return;
    int n = gw / H, h = gw - n * H;
    const float* xr = xl + (long)n * H * C + h * C;
    float s1 = 0.f, s2 = 0.f;
    for (int c = lane; c < C; c += 32) {
        float xv = xr[c];
        s1 += xv * as_[h * C + c];
        s2 += xv * ad_[h * C + c];
    }
#pragma unroll
    for (int o = 16; o; o >>= 1) {
        s1 += __shfl_down_sync(0xffffffffu, s1, o);
        s2 += __shfl_down_sync(0xffffffffu, s2, o);
    }
    if (lane == 0) { d_als[n * H + h] = s1; d_ald[n * H + h] = s2; }
}

// ---------------- GAT aggregation (softmax-max + weighted gather) ----
template <int H, int C>
__global__ void k_aggregate(const float* __restrict__ xl,
                            const float* __restrict__ bias,
                            float* __restrict__ out) {
    constexpr int HC = H * C;
    int n = blockIdx.x;
    int t = threadIdx.x;                 // HC/4 threads, float4 each
    int h = (t * 4) / C;
    float aldn = d_ald[n * H + h];
    int e0 = d_rp[n], e1 = d_rp[n + 1];

    float mx = -1e30f;
    for (int e = e0; e < e1; e++) {
        int s = d_esrc[e];
        float v = d_als[s * H + h] + aldn;
        v = v > 0.f ? v : 0.2f * v;
        mx = fmaxf(mx, v);
    }
    float4 acc = make_float4(0.f, 0.f, 0.f, 0.f);
    float den = 0.f;
    const float4* x4 = (const float4*)xl;
    for (int e = e0; e < e1; e++) {
        int s = d_esrc[e];
        float v = d_als[s * H + h] + aldn;
        v = v > 0.f ? v : 0.2f * v;
        float w = __expf(v - mx);
        den += w;
        float4 xv = x4[(long)s * (HC / 4) + t];
        acc.x += w * xv.x; acc.y += w * xv.y;
        acc.z += w * xv.z; acc.w += w * xv.w;
    }
    float inv = 1.f / (den + 1e-16f);
    float4 bb = ((const float4*)bias)[t];
    float4 r;
    r.x = acc.x * inv + bb.x;
    r.y = acc.y * inv + bb.y;
    r.z = acc.z * inv + bb.z;
    r.w = acc.w * inv + bb.w;
    ((float4*)out)[(long)n * (HC / 4) + t] = r;
}

// ---------------- epilogue: optional ELU, LayerNorm, optional residual
template <int D>
__global__ void k_ln(const float* __restrict__ in, const float* __restrict__ g,
                     const float* __restrict__ b, const float* __restrict__ res,
                     float* __restrict__ out, float* __restrict__ res_out, int elu) {
    constexpr int T = D / 4;
    int n = blockIdx.x, t = threadIdx.x;
    float4 v = ((const float4*)in)[(long)n * T + t];
    if (elu) {
        v.x = v.x > 0.f ? v.x : expm1f(v.x);
        v.y = v.y > 0.f ? v.y : expm1f(v.y);
        v.z = v.z > 0.f ? v.z : expm1f(v.z);
        v.w = v.w > 0.f ? v.w : expm1f(v.w);
    }
    float sum = v.x + v.y + v.z + v.w;
    float sq  = v.x * v.x + v.y * v.y + v.z * v.z + v.w * v.w;
#pragma unroll
    for (int o = 16; o; o >>= 1) {
        sum += __shfl_down_sync(0xffffffffu, sum, o);
        sq  += __shfl_down_sync(0xffffffffu, sq, o);
    }
    __shared__ float a1[T / 32], a2[T / 32];
    int lane = t & 31, w = t >> 5;
    if (lane == 0) { a1[w] = sum; a2[w] = sq; }
    __syncthreads();
    float tot = 0.f, totsq = 0.f;
#pragma unroll
    for (int i = 0; i < T / 32; i++) { tot += a1[i]; totsq += a2[i]; }
    float mu = tot / (float)D;
    float var = totsq / (float)D - mu * mu;
    float rstd = rsqrtf(var + 1e-5f);
    float4 gg = ((const float4*)g)[t];
    float4 bb = ((const float4*)b)[t];
    float4 o;
    o.x = (v.x - mu) * rstd * gg.x + bb.x;
    o.y = (v.y - mu) * rstd * gg.y + bb.y;
    o.z = (v.z - mu) * rstd * gg.z + bb.z;
    o.w = (v.w - mu) * rstd * gg.w + bb.w;
    if (res) {
        float4 rr = ((const float4*)res)[(long)n * T + t];
        o.x += rr.x; o.y += rr.y; o.z += rr.z; o.w += rr.w;
    }
    ((float4*)out)[(long)n * T + t] = o;
    if (res_out) ((float4*)res_out)[(long)n * T + t] = o;
}

// ---------------- dense MHA: tf32 mma flash attention ---------------
// block: 64 queries x one head; 4 warps, each warp owns 16 query rows.
__global__ void __launch_bounds__(128) k_attn_mma(const float* __restrict__ Q,
                                                  const float* __restrict__ K,
                                                  const float* __restrict__ V,
                                                  float* __restrict__ O) {
    __shared__ float Ks[64][36];      // tf32 bits
    __shared__ float Vs[64][36];      // tf32 bits
    __shared__ float Ps[4][16][68];   // per-warp P tile, tf32 bits

    int h = blockIdx.y;
    int q0 = blockIdx.x * 64;
    int t = threadIdx.x, w = t >> 5, lane = t & 31;
    int gid = lane >> 2, tig = lane & 3;

    // Q fragments (pre-scaled), resident for whole kernel
    const float sc = 0.17677669529663687f;  // 1/sqrt(32)
    unsigned aq[4][4];
    int qrow = q0 + w * 16 + gid;
#pragma unroll
    for (int kk = 0; kk < 4; kk++) {
        float f0 = Q[(long)qrow * 256 + h * 32 + kk * 8 + tig] * sc;
        float f1 = Q[(long)(qrow + 8) * 256 + h * 32 + kk * 8 + tig] * sc;
        float f2 = Q[(long)qrow * 256 + h * 32 + kk * 8 + tig + 4] * sc;
        float f3 = Q[(long)(qrow + 8) * 256 + h * 32 + kk * 8 + tig + 4] * sc;
        aq[kk][0] = f2tf(f0); aq[kk][1] = f2tf(f1);
        aq[kk][2] = f2tf(f2); aq[kk][3] = f2tf(f3);
    }

    float o[4][4];
#pragma unroll
    for (int nt = 0; nt < 4; nt++)
#pragma unroll
        for (int i = 0; i < 4; i++) o[nt][i] = 0.f;
    float m0 = -1e30f, m1 = -1e30f, l0 = 0.f, l1 = 0.f;

    for (int kt0 = 0; kt0 < NN; kt0 += 64) {
        __syncthreads();
        // load K,V tiles (cvt tf32 at store)
#pragma unroll
        for (int i = 0; i < 4; i++) {
            int fi = t + i * 128;
            int row = fi >> 3, c4 = fi & 7;
            float4 kv = *(const float4*)&K[(long)(kt0 + row) * 256 + h * 32 + c4 * 4];
            float4 u;
            u.x = __uint_as_float(f2tf(kv.x));
            u.y = __uint_as_float(f2tf(kv.y));
            u.z = __uint_as_float(f2tf(kv.z));
            u.w = __uint_as_float(f2tf(kv.w));
            *(float4*)&Ks[row][c4 * 4] = u;
            float4 vv = *(const float4*)&V[(long)(kt0 + row) * 256 + h * 32 + c4 * 4];
            float4 u2;
            u2.x = __uint_as_float(f2tf(vv.x));
            u2.y = __uint_as_float(f2tf(vv.y));
            u2.z = __uint_as_float(f2tf(vv.z));
            u2.w = __uint_as_float(f2tf(vv.w));
            *(float4*)&Vs[row][c4 * 4] = u2;
        }
        __syncthreads();

        // S = Q @ K^T : per warp 16 x 64
        float s[8][4];
#pragma unroll
        for (int nt = 0; nt < 8; nt++) {
#pragma unroll
            for (int i = 0; i < 4; i++) s[nt][i] = 0.f;
#pragma unroll
            for (int kk = 0; kk < 4; kk++) {
                unsigned b0 = __float_as_uint(Ks[nt * 8 + gid][kk * 8 + tig]);
                unsigned b1 = __float_as_uint(Ks[nt * 8 + gid][kk * 8 + tig + 4]);
                mma_tf32(s[nt], aq[kk][0], aq[kk][1], aq[kk][2], aq[kk][3], b0, b1);
            }
        }

        // online softmax (2 rows per thread, cols spread over 4-lane group)
        float tm0 = -1e30f, tm1 = -1e30f;
#pragma unroll
        for (int nt = 0; nt < 8; nt++) {
            tm0 = fmaxf(tm0, fmaxf(s[nt][0], s[nt][1]));
            tm1 = fmaxf(tm1, fmaxf(s[nt][2], s[nt][3]));
        }
        tm0 = fmaxf(tm0, __shfl_xor_sync(0xffffffffu, tm0, 1));
        tm0 = fmaxf(tm0, __shfl_xor_sync(0xffffffffu, tm0, 2));
        tm1 = fmaxf(tm1, __shfl_xor_sync(0xffffffffu, tm1, 1));
        tm1 = fmaxf(tm1, __shfl_xor_sync(0xffffffffu, tm1, 2));
        float nm0 = fmaxf(m0, tm0), nm1 = fmaxf(m1, tm1);
        float c0 = __expf(m0 - nm0), c1 = __expf(m1 - nm1);

        float rs0 = 0.f, rs1 = 0.f;
#pragma unroll
        for (int nt = 0; nt < 8; nt++) {
            float p0 = __expf(s[nt][0] - nm0);
            float p1 = __expf(s[nt][1] - nm0);
            float p2 = __expf(s[nt][2] - nm1);
            float p3 = __expf(s[nt][3] - nm1);
            rs0 += p0 + p1;
            rs1 += p2 + p3;
            *(float2*)&Ps[w][gid][nt * 8 + 2 * tig] =
                make_float2(__uint_as_float(f2tf(p0)), __uint_as_float(f2tf(p1)));
            *(float2*)&Ps[w][gid + 8][nt * 8 + 2 * tig] =
                make_float2(__uint_as_float(f2tf(p2)), __uint_as_float(f2tf(p3)));
        }
        rs0 += __shfl_xor_sync(0xffffffffu, rs0, 1);
        rs0 += __shfl_xor_sync(0xffffffffu, rs0, 2);
        rs1 += __shfl_xor_sync(0xffffffffu, rs1, 1);
        rs1 += __shfl_xor_sync(0xffffffffu, rs1, 2);
        l0 = l0 * c0 + rs0;
        l1 = l1 * c1 + rs1;
#pragma unroll
        for (int nt = 0; nt < 4; nt++) {
            o[nt][0] *= c0; o[nt][1] *= c0;
            o[nt][2] *= c1; o[nt][3] *= c1;
        }
        m0 = nm0; m1 = nm1;
        __syncwarp();

        // O += P @ V
#pragma unroll
        for (int kt = 0; kt < 8; kt++) {
            unsigned a0 = __float_as_uint(Ps[w][gid][kt * 8 + tig]);
            unsigned a1 = __float_as_uint(Ps[w][gid + 8][kt * 8 + tig]);
            unsigned a2 = __float_as_uint(Ps[w][gid][kt * 8 + tig + 4]);
            unsigned a3 = __float_as_uint(Ps[w][gid + 8][kt * 8 + tig + 4]);
#pragma unroll
            for (int nt = 0; nt < 4; nt++) {
                unsigned b0 = __float_as_uint(Vs[kt * 8 + tig][nt * 8 + gid]);
                unsigned b1 = __float_as_uint(Vs[kt * 8 + tig + 4][nt * 8 + gid]);
                mma_tf32(o[nt], a0, a1, a2, a3, b0, b1);
            }
        }
    }

    float inv0 = 1.f / l0, inv1 = 1.f / l1;
#pragma unroll
    for (int nt = 0; nt < 4; nt++) {
        int col = h * 32 + nt * 8 + 2 * tig;
        *(float2*)&O[(long)qrow * 256 + col] =
            make_float2(o[nt][0] * inv0, o[nt][1] * inv0);
        *(float2*)&O[(long)(qrow + 8) * 256 + col] =
            make_float2(o[nt][2] * inv1, o[nt][3] * inv1);
    }
}

// ---------------- launch -----------------------------------------------
extern "C" void kernel_launch(void* const* d_in, const int* in_sizes, int n_in,
                              void* d_out, int out_size) {
    const float* x   = (const float*)d_in[0];
    const void*  ei  = d_in[1];
    const float* W0  = (const float*)d_in[2];
    const float* as0 = (const float*)d_in[3];
    const float* ad0 = (const float*)d_in[4];
    const float* b0  = (const float*)d_in[5];
    const float* W1  = (const float*)d_in[6];
    const float* as1 = (const float*)d_in[7];
    const float* ad1 = (const float*)d_in[8];
    const float* b1  = (const float*)d_in[9];
    const float* W2  = (const float*)d_in[10];
    const float* as2 = (const float*)d_in[11];
    const float* ad2 = (const float*)d_in[12];
    const float* b2  = (const float*)d_in[13];
    const float* g0  = (const float*)d_in[14];
    const float* be0 = (const float*)d_in[15];
    const float* g1  = (const float*)d_in[16];
    const float* be1 = (const float*)d_in[17];
    const float* g2  = (const float*)d_in[18];
    const float* be2 = (const float*)d_in[19];
    const float* wq  = (const float*)d_in[20];
    const float* bq  = (const float*)d_in[21];
    const float* wk  = (const float*)d_in[22];
    const float* bk  = (const float*)d_in[23];
    const float* wv  = (const float*)d_in[24];
    const float* bv  = (const float*)d_in[25];
    const float* wo  = (const float*)d_in[26];
    const float* bo  = (const float*)d_in[27];
    float* out = (float*)d_out;

    // CSR build
    k_detect<<<1, 32>>>((const unsigned*)ei);
    k_zero_cnt<<<(NN + 255) / 256, 256>>>();
    k_count<<<(ETOT + 255) / 256, 256>>>(ei);
    k_scan<<<1, 1024>>>();
    k_scatter<<<(ETOT + 255) / 256, 256>>>(ei);

    // ---- layer 0: 128 -> 4x128 ----
    k_gemm_tc<<<dim3(512 / 64, NN / 128), 256>>>(x, W0, nullptr, d_xl, NN, 128, 512);
    k_coef<<<(NN * 4 * 32 + 255) / 256, 256>>>(d_xl, as0, ad0, 4, 128);
    k_aggregate<4, 128><<<NN, 128>>>(d_xl, b0, d_gat);
    k_ln<512><<<NN, 128>>>(d_gat, g0, be0, nullptr, d_h, d_res, 1);

    // ---- layer 1: 512 -> 4x128, residual ----
    k_gemm_tc<<<dim3(512 / 64, NN / 128), 256>>>(d_h, W1, nullptr, d_xl, NN, 512, 512);
    k_coef<<<(NN * 4 * 32 + 255) / 256, 256>>>(d_xl, as1, ad1, 4, 128);
    k_aggregate<4, 128><<<NN, 128>>>(d_xl, b1, d_gat);
    k_ln<512><<<NN, 128>>>(d_gat, g1, be1, d_res, d_h, nullptr, 1);

    // ---- layer 2: 512 -> 1x256, no ELU ----
    k_gemm_tc<<<dim3(256 / 64, NN / 128), 256>>>(d_h, W2, nullptr, d_xl, NN, 512, 256);
    k_coef<<<(NN * 1 * 32 + 255) / 256, 256>>>(d_xl, as2, ad2, 1, 256);
    k_aggregate<1, 256><<<NN, 64>>>(d_xl, b2, d_gat);
    k_ln<256><<<NN, 64>>>(d_gat, g2, be2, nullptr, d_h2, nullptr, 0);

    // ---- dense MHA ----
    k_gemm_tc<<<dim3(256 / 64, NN / 128), 256>>>(d_h2, wq, bq, d_Q,  NN, 256, 256);
    k_gemm_tc<<<dim3(256 / 64, NN / 128), 256>>>(d_h2, wk, bk, d_Kb, NN, 256, 256);
    k_gemm_tc<<<dim3(256 / 64, NN / 128), 256>>>(d_h2, wv, bv, d_Vb, NN, 256, 256);
    k_attn_mma<<<dim3(NN / 64, 8), 128>>>(d_Q, d_Kb, d_Vb, d_att);
    k_gemm_tc<<<dim3(256 / 64, NN / 128), 256>>>(d_att, wo, bo, out, NN, 256, 256);
}